// round 7
// baseline (speedup 1.0000x reference)
#include <cuda_runtime.h>
#include <cuda_bf16.h>
#include <math.h>
#include <stdint.h>

#define OBS_LEN 20
#define BATCH   2048
#define IN_DIM  512
#define HID     1024
#define G4      4096
#define K3      3072          // 3*HID split-K concat
#define CHUNK   64            // K per pipeline chunk (128B bf16 rows)
#define NCHUNK  48            // K3/CHUNK (divisible by 3 for unroll-3 stage fold)
#define TILE_M  128
#define TILE_N  128
#define ROWB    144           // 128 data + 16 pad -> conflict-free ldsm phases
#define STAGE_BYTES (256 * ROWB)          // 36864
#define NSTAGE  3
#define SMEM_DYN (NSTAGE * STAGE_BYTES)   // 110592 (2 CTAs = 221KB <= 228KB)

// ---------------------------------------------------------------------------
// Device scratch
// ---------------------------------------------------------------------------
__device__ __align__(16) float          g_Wc[G4 * 2];
__device__ __align__(16) float          g_bc[G4];
__device__ __align__(16) __nv_bfloat16  g_Wperm[(size_t)G4 * K3];  // 25 MB
__device__ __align__(16) __nv_bfloat16  g_A0[(size_t)BATCH * K3];  // 12.6 MB
__device__ __align__(16) __nv_bfloat16  g_A1[(size_t)BATCH * K3];
__device__ __align__(16) float          g_cbuf[(size_t)BATCH * HID];

// ---------------------------------------------------------------------------
// Helpers (family-portable PTX only: cp.async / ldmatrix / mma.sync)
// ---------------------------------------------------------------------------
__device__ __forceinline__ uint32_t smem_u32(const void* p) {
    uint32_t a;
    asm("{ .reg .u64 t; cvta.to.shared.u64 t, %1; cvt.u32.u64 %0, t; }"
        : "=r"(a) : "l"(p));
    return a;
}
__device__ __forceinline__ void cp16(uint32_t dst, const void* src) {
    asm volatile("cp.async.cg.shared.global [%0], [%1], 16;"
                 :: "r"(dst), "l"(src) : "memory");
}
__device__ __forceinline__ void ldsm4(uint32_t* r, uint32_t addr) {
    asm volatile("ldmatrix.sync.aligned.m8n8.x4.shared.b16 {%0,%1,%2,%3}, [%4];"
                 : "=r"(r[0]), "=r"(r[1]), "=r"(r[2]), "=r"(r[3]) : "r"(addr));
}
__device__ __forceinline__ void mma16816(float* d, const uint32_t* a,
                                         uint32_t b0, uint32_t b1) {
    asm volatile(
        "mma.sync.aligned.m16n8k16.row.col.f32.bf16.bf16.f32 "
        "{%0,%1,%2,%3},{%4,%5,%6,%7},{%8,%9},{%0,%1,%2,%3};"
        : "+f"(d[0]), "+f"(d[1]), "+f"(d[2]), "+f"(d[3])
        : "r"(a[0]), "r"(a[1]), "r"(a[2]), "r"(a[3]), "r"(b0), "r"(b1));
}
__device__ __forceinline__ float sigm(float x) {
    return __fdividef(1.f, 1.f + __expf(-x));
}
__device__ __forceinline__ float tanh_f(float x) {
    return __fdividef(2.f, 1.f + __expf(-2.f * x)) - 1.f;
}

// ---------------------------------------------------------------------------
// Prep 1: fold embedding into per-gate input weights (Wc [G4][2], bc [G4]).
// ---------------------------------------------------------------------------
__global__ void prep_wc_kernel(const float* __restrict__ W_emb,
                               const float* __restrict__ b_emb,
                               const float* __restrict__ W_ih,
                               const float* __restrict__ b_ih,
                               const float* __restrict__ b_hh) {
    int warp = (blockIdx.x * blockDim.x + threadIdx.x) >> 5;
    int lane = threadIdx.x & 31;
    if (warp >= G4) return;
    const float* wrow = W_ih + (size_t)warp * IN_DIM;
    float s0 = 0.f, s1 = 0.f, sb = 0.f;
    for (int h = lane; h < IN_DIM; h += 32) {
        float w = wrow[h];
        s0 += w * W_emb[h * 2 + 0];
        s1 += w * W_emb[h * 2 + 1];
        sb += w * b_emb[h];
    }
#pragma unroll
    for (int o = 16; o > 0; o >>= 1) {
        s0 += __shfl_down_sync(0xffffffffu, s0, o);
        s1 += __shfl_down_sync(0xffffffffu, s1, o);
        sb += __shfl_down_sync(0xffffffffu, sb, o);
    }
    if (lane == 0) {
        g_Wc[warp * 2 + 0] = s0;
        g_Wc[warp * 2 + 1] = s1;
        g_bc[warp] = sb + b_ih[warp] + b_hh[warp];
    }
}

// ---------------------------------------------------------------------------
// Prep 2: permuted bf16-split B' = [W_hi | W_lo | W_hi].
// Row permutation matches the 64x64-warp-tile mma d-fragment layout:
//   pr = y*128 + c ; warpN = c>>6 ; cw = c&63 ; t = cw>>3 (n8-tile) ; w = cw&7
//   gate = t&3 ; unit = y*32 + warpN*16 + (t>>2)*8 + w ; j = gate*1024 + unit
// ---------------------------------------------------------------------------
__global__ void prep_wperm_kernel(const float* __restrict__ W_hh) {
    int pr = blockIdx.x;
    int y = pr >> 7, c = pr & 127;
    int warpN = c >> 6, cw = c & 63;
    int t = cw >> 3, w = cw & 7;
    int gate = t & 3;
    int u = (y << 5) + (warpN << 4) + ((t >> 2) << 3) + w;
    int j = (gate << 10) + u;
    const float* wrow = W_hh + (size_t)j * HID;
    __nv_bfloat16* orow = g_Wperm + (size_t)pr * K3;
    for (int kk = threadIdx.x * 4; kk < K3; kk += blockDim.x * 4) {
        int seg = kk >> 10;
        int ksrc = kk - (seg << 10);
        float4 ww = *(const float4*)(wrow + ksrc);
        float v[4] = {ww.x, ww.y, ww.z, ww.w};
        union { __nv_bfloat16 b[4]; uint2 u2; } out;
#pragma unroll
        for (int x = 0; x < 4; x++) {
            __nv_bfloat16 hi = __float2bfloat16(v[x]);
            if (seg == 1) out.b[x] = __float2bfloat16(v[x] - __bfloat162float(hi));
            else          out.b[x] = hi;
        }
        *(uint2*)(orow + kk) = out.u2;
    }
}

// ---------------------------------------------------------------------------
// Prep 3: h0 -> A'(step 0) = [hi | hi | lo]
// ---------------------------------------------------------------------------
__global__ void init_h0_kernel(const float* __restrict__ h0) {
    int v = blockIdx.x * blockDim.x + threadIdx.x;
    int e = v * 4;
    int b = e >> 10, k = e & 1023;
    float4 h = *(const float4*)(h0 + e);
    float vv[4] = {h.x, h.y, h.z, h.w};
    union { __nv_bfloat16 b[4]; uint2 u2; } phi, plo;
#pragma unroll
    for (int x = 0; x < 4; x++) {
        __nv_bfloat16 hi = __float2bfloat16(vv[x]);
        phi.b[x] = hi;
        plo.b[x] = __float2bfloat16(vv[x] - __bfloat162float(hi));
    }
    __nv_bfloat16* row = g_A0 + (size_t)b * K3;
    *(uint2*)(row + k)        = phi.u2;
    *(uint2*)(row + 1024 + k) = phi.u2;
    *(uint2*)(row + 2048 + k) = plo.u2;
}

// ---------------------------------------------------------------------------
// Fused LSTM step: 128x128 HMMA GEMM over K'=3072 + in-register cell update.
// 4 warps (2x2, warp tile 64x64), CHUNK=64, NSTAGE=3, register-fragment
// double buffering (CUTLASS sm80-style mainloop).
// ---------------------------------------------------------------------------
__global__ __launch_bounds__(128, 2) void lstm_step_kernel(
    const __nv_bfloat16* __restrict__ Acur,
    __nv_bfloat16* __restrict__ Anext,
    const float* __restrict__ obs_t,
    float* __restrict__ hout) {
    extern __shared__ __align__(128) char dyn[];
    const int tid = threadIdx.x;
    const int wid = tid >> 5, lane = tid & 31;
    const int warpM = wid >> 1, warpN = wid & 1;   // 2 x 2 warp grid
    const int bRow = blockIdx.x * TILE_M;
    const int prBase = blockIdx.y * TILE_N;

    const uint32_t base = smem_u32(dyn);

    // ldmatrix per-thread address components
    const int g = lane >> 3, jj = lane & 7;
    // A tile: rows (g&1)*8 + jj, k-16B-quarter base = g>>1
    const uint32_t aoff = (uint32_t)((warpM * 64 + ((g & 1) << 3) + jj) * ROWB
                                     + ((g >> 1) << 4));
    // B tile: rows (g>>1)*8 + jj, k-16B base = g&1 (B rows start at 128*ROWB)
    const uint32_t boff = (uint32_t)((128 + warpN * 64 + ((g >> 1) << 3) + jj) * ROWB
                                     + ((g & 1) << 4));

    float acc[4][8][4];
#pragma unroll
    for (int m = 0; m < 4; m++)
#pragma unroll
        for (int n = 0; n < 8; n++)
#pragma unroll
            for (int x = 0; x < 4; x++) acc[m][n][x] = 0.f;

    // loader: thread tid loads A row tid and B row tid (128B each = 8 cp16),
    // column order rotated by (tid>>3) to avoid store bank conflicts.
    const __nv_bfloat16* asrc = Acur + (size_t)(bRow + tid) * K3;
    const __nv_bfloat16* bsrc = g_Wperm + (size_t)(prBase + tid) * K3;
    const uint32_t adst = base + tid * ROWB;
    const uint32_t bdst = base + (128 + tid) * ROWB;
    const int crot = tid >> 3;

#define LOAD_CHUNK(SO, K0)                                                 \
    {                                                                      \
        _Pragma("unroll")                                                  \
        for (int jv = 0; jv < 8; jv++) {                                   \
            int cc = (jv + crot) & 7;                                      \
            cp16(adst + (SO) + cc * 16, asrc + (K0) + cc * 8);             \
            cp16(bdst + (SO) + cc * 16, bsrc + (K0) + cc * 8);             \
        }                                                                  \
    }

    // Prologue: chunks 0,1 into stages 0,1
    LOAD_CHUNK(0, 0);
    asm volatile("cp.async.commit_group;" ::: "memory");
    LOAD_CHUNK(STAGE_BYTES, CHUNK);
    asm volatile("cp.async.commit_group;" ::: "memory");

    uint32_t aF[2][16], bF[2][16];

#pragma unroll 3
    for (int it = 0; it < NCHUNK; ++it) {
        asm volatile("cp.async.wait_group 1;" ::: "memory");
        __syncthreads();
        const uint32_t so = (uint32_t)(it % 3) * STAGE_BYTES;

        // Prefetch chunk it+2 into the stage freed last iteration.
        if (it + 2 < NCHUNK) {
            const uint32_t so2 = (uint32_t)((it + 2) % 3) * STAGE_BYTES;
            const int k0 = (it + 2) * CHUNK;
            LOAD_CHUNK(so2, k0);
        }
        asm volatile("cp.async.commit_group;" ::: "memory");

        // kt=0 fragments
#pragma unroll
        for (int m = 0; m < 4; m++) ldsm4(&aF[0][m * 4], base + so + aoff + m * 16 * ROWB);
#pragma unroll
        for (int nb = 0; nb < 4; nb++) ldsm4(&bF[0][nb * 4], base + so + boff + nb * 16 * ROWB);

#pragma unroll
        for (int kt = 0; kt < 4; kt++) {
            const int cur = kt & 1, nxt = cur ^ 1;
            if (kt < 3) {
                const uint32_t aA = base + so + aoff + (kt + 1) * 32;
                const uint32_t aB = base + so + boff + (kt + 1) * 32;
#pragma unroll
                for (int m = 0; m < 4; m++) ldsm4(&aF[nxt][m * 4], aA + m * 16 * ROWB);
#pragma unroll
                for (int nb = 0; nb < 4; nb++) ldsm4(&bF[nxt][nb * 4], aB + nb * 16 * ROWB);
            }
#pragma unroll
            for (int m = 0; m < 4; m++)
#pragma unroll
                for (int n = 0; n < 8; n++)
                    mma16816(acc[m][n], &aF[cur][m * 4],
                             bF[cur][(n >> 1) * 4 + (n & 1) * 2],
                             bF[cur][(n >> 1) * 4 + (n & 1) * 2 + 1]);
        }
    }
#undef LOAD_CHUNK

    // ------------------ fused LSTM epilogue (all in registers) ------------------
    // Thread owns units u0 + h*8 + i (h,i in {0,1}) x all 4 gates;
    // gate g of unit-half h lives in n-tile t = h*4 + g.
    const int q = lane & 3;
    const int u0 = blockIdx.y * 32 + warpN * 16 + 2 * q;
    const int rbase = bRow + warpM * 64 + (lane >> 2);

    float wcx[2][2][4], wcy[2][2][4], bcv[2][2][4];
#pragma unroll
    for (int h = 0; h < 2; h++)
#pragma unroll
        for (int i = 0; i < 2; i++)
#pragma unroll
            for (int gg = 0; gg < 4; gg++) {
                int j = (gg << 10) + u0 + h * 8 + i;
                float2 w = *(const float2*)(g_Wc + j * 2);
                wcx[h][i][gg] = w.x; wcy[h][i][gg] = w.y; bcv[h][i][gg] = g_bc[j];
            }

#pragma unroll
    for (int m = 0; m < 4; m++)
#pragma unroll
        for (int s = 0; s < 2; s++) {
            int b = rbase + m * 16 + s * 8;
            float2 ob = *(const float2*)(obs_t + b * 2);
            float* crow = g_cbuf + (size_t)b * HID;
#pragma unroll
            for (int h = 0; h < 2; h++) {
                int ub = u0 + h * 8;
                float2 cold = *(const float2*)(crow + ub);
                float cprev[2] = {cold.x, cold.y};
                float cn[2], hn[2];
#pragma unroll
                for (int i = 0; i < 2; i++) {
                    float gv[4];
#pragma unroll
                    for (int gg = 0; gg < 4; gg++)
                        gv[gg] = acc[m][h * 4 + gg][s * 2 + i]
                               + ob.x * wcx[h][i][gg] + ob.y * wcy[h][i][gg]
                               + bcv[h][i][gg];
                    float ig = sigm(gv[0]);
                    float fg = sigm(gv[1]);
                    float gc = tanh_f(gv[2]);
                    float og = sigm(gv[3]);
                    cn[i] = fg * cprev[i] + ig * gc;
                    hn[i] = og * tanh_f(cn[i]);
                }
                *(float2*)(crow + ub) = make_float2(cn[0], cn[1]);
                if (hout)
                    *(float2*)(hout + (size_t)b * HID + ub) = make_float2(hn[0], hn[1]);

                union { __nv_bfloat16 hv[2]; uint32_t u; } phi, plo;
#pragma unroll
                for (int i = 0; i < 2; i++) {
                    __nv_bfloat16 hi = __float2bfloat16(hn[i]);
                    phi.hv[i] = hi;
                    plo.hv[i] = __float2bfloat16(hn[i] - __bfloat162float(hi));
                }
                __nv_bfloat16* ar = Anext + (size_t)b * K3 + ub;
                *(uint32_t*)(ar)        = phi.u;
                *(uint32_t*)(ar + 1024) = phi.u;
                *(uint32_t*)(ar + 2048) = plo.u;
            }
        }
}

// ---------------------------------------------------------------------------
extern "C" void kernel_launch(void* const* d_in, const int* in_sizes, int n_in,
                              void* d_out, int out_size) {
    const float* obs   = (const float*)d_in[0];
    const float* h0    = (const float*)d_in[1];
    const float* c0    = (const float*)d_in[2];
    const float* W_emb = (const float*)d_in[3];
    const float* b_emb = (const float*)d_in[4];
    const float* W_ih  = (const float*)d_in[5];
    const float* W_hh  = (const float*)d_in[6];
    const float* b_ih  = (const float*)d_in[7];
    const float* b_hh  = (const float*)d_in[8];

    float* cbuf;
    __nv_bfloat16 *a0, *a1;
    cudaGetSymbolAddress((void**)&cbuf, g_cbuf);
    cudaGetSymbolAddress((void**)&a0, g_A0);
    cudaGetSymbolAddress((void**)&a1, g_A1);

    cudaMemcpyAsync(cbuf, c0, sizeof(float) * BATCH * HID,
                    cudaMemcpyDeviceToDevice, 0);

    prep_wc_kernel<<<512, 256>>>(W_emb, b_emb, W_ih, b_ih, b_hh);
    prep_wperm_kernel<<<G4, 256>>>(W_hh);
    init_h0_kernel<<<BATCH * HID / 4 / 256, 256>>>(h0);

    cudaFuncSetAttribute(lstm_step_kernel,
                         cudaFuncAttributeMaxDynamicSharedMemorySize, SMEM_DYN);

    dim3 grid(BATCH / TILE_M, G4 / TILE_N);   // (16, 32)
    __nv_bfloat16* bufs[2] = {a0, a1};
    for (int t = 0; t < OBS_LEN; t++) {
        lstm_step_kernel<<<grid, 128, SMEM_DYN>>>(
            bufs[t & 1], bufs[(t + 1) & 1],
            obs + (size_t)t * BATCH * 2,
            (t == OBS_LEN - 1) ? (float*)d_out : nullptr);
    }
}

// round 8
// speedup vs baseline: 1.6769x; 1.6769x over previous
#include <cuda_runtime.h>
#include <cuda_bf16.h>
#include <math.h>
#include <stdint.h>
#include <string.h>

#define OBS_LEN 20
#define BATCH   2048
#define IN_DIM  512
#define HID     1024
#define G4      4096
#define K3      3072          // 3*HID split-K concat
#define CHUNK   32            // K per pipeline chunk
#define NCHUNK  96            // K3/CHUNK
#define TILE_M  128
#define ROWB    80            // A smem row stride (64 data + 16 pad)
#define STAGE_BYTES (128 * ROWB)          // A-only stage: 10240
#define NSTAGE  4
#define SMEM_DYN (NSTAGE * STAGE_BYTES)   // 40960

// ---------------------------------------------------------------------------
// Device scratch
// ---------------------------------------------------------------------------
__device__ __align__(16) float          g_Wc[G4 * 2];
__device__ __align__(16) float          g_bc[G4];
// B in mma-fragment order: [wb=ntile*4+warpN][ktstep=0..191][lane][8 regs]
// + 64 uint4 padding (one extra kt-step) for the tail prefetch.
#define WFRAG_U4 ((size_t)128 * 192 * 32 * 2 + 64)
__device__ __align__(16) uint4          g_Wfrag[WFRAG_U4];              // ~25 MB
__device__ __align__(16) __nv_bfloat16  g_A0[(size_t)BATCH * K3];       // 12.6 MB
__device__ __align__(16) __nv_bfloat16  g_A1[(size_t)BATCH * K3];
__device__ __align__(16) float          g_cbuf[(size_t)BATCH * HID];

// ---------------------------------------------------------------------------
// Helpers (family-portable PTX only: cp.async / ldmatrix / mma.sync)
// ---------------------------------------------------------------------------
__device__ __forceinline__ uint32_t smem_u32(const void* p) {
    uint32_t a;
    asm("{ .reg .u64 t; cvta.to.shared.u64 t, %1; cvt.u32.u64 %0, t; }"
        : "=r"(a) : "l"(p));
    return a;
}
__device__ __forceinline__ void cp16(uint32_t dst, const void* src) {
    asm volatile("cp.async.cg.shared.global [%0], [%1], 16;"
                 :: "r"(dst), "l"(src) : "memory");
}
__device__ __forceinline__ void ldsm4(uint32_t* r, uint32_t addr) {
    asm volatile("ldmatrix.sync.aligned.m8n8.x4.shared.b16 {%0,%1,%2,%3}, [%4];"
                 : "=r"(r[0]), "=r"(r[1]), "=r"(r[2]), "=r"(r[3]) : "r"(addr));
}
__device__ __forceinline__ void mma16816(float* d, const uint32_t* a,
                                         uint32_t b0, uint32_t b1) {
    asm volatile(
        "mma.sync.aligned.m16n8k16.row.col.f32.bf16.bf16.f32 "
        "{%0,%1,%2,%3},{%4,%5,%6,%7},{%8,%9},{%0,%1,%2,%3};"
        : "+f"(d[0]), "+f"(d[1]), "+f"(d[2]), "+f"(d[3])
        : "r"(a[0]), "r"(a[1]), "r"(a[2]), "r"(a[3]), "r"(b0), "r"(b1));
}
__device__ __forceinline__ float sigm(float x) {
    return __fdividef(1.f, 1.f + __expf(-x));
}
__device__ __forceinline__ float tanh_f(float x) {
    return __fdividef(2.f, 1.f + __expf(-2.f * x)) - 1.f;
}

// ---------------------------------------------------------------------------
// Prep 1: fold embedding into per-gate input weights (Wc [G4][2], bc [G4]).
// ---------------------------------------------------------------------------
__global__ void prep_wc_kernel(const float* __restrict__ W_emb,
                               const float* __restrict__ b_emb,
                               const float* __restrict__ W_ih,
                               const float* __restrict__ b_ih,
                               const float* __restrict__ b_hh) {
    int warp = (blockIdx.x * blockDim.x + threadIdx.x) >> 5;
    int lane = threadIdx.x & 31;
    if (warp >= G4) return;
    const float* wrow = W_ih + (size_t)warp * IN_DIM;
    float s0 = 0.f, s1 = 0.f, sb = 0.f;
    for (int h = lane; h < IN_DIM; h += 32) {
        float w = wrow[h];
        s0 += w * W_emb[h * 2 + 0];
        s1 += w * W_emb[h * 2 + 1];
        sb += w * b_emb[h];
    }
#pragma unroll
    for (int o = 16; o > 0; o >>= 1) {
        s0 += __shfl_down_sync(0xffffffffu, s0, o);
        s1 += __shfl_down_sync(0xffffffffu, s1, o);
        sb += __shfl_down_sync(0xffffffffu, sb, o);
    }
    if (lane == 0) {
        g_Wc[warp * 2 + 0] = s0;
        g_Wc[warp * 2 + 1] = s1;
        g_bc[warp] = sb + b_ih[warp] + b_hh[warp];
    }
}

// ---------------------------------------------------------------------------
// Prep 2: build B in exact mma b-fragment order with bf16 split
//   [W_hi | W_lo | W_hi] along the K3 axis.
// For wb = ntile*4+warpN, ktstep = it*2+kt, lane, reg = nb*2+half:
//   gate = nb ; unit = ntile*32 + warpN*8 + (lane>>2) ; j = gate*1024+unit
//   k    = ktstep*16 + half*8 + (lane&3)*2 + i   (i = 0,1 packed in uint32)
//   seg  = k>>10 (0:hi 1:lo 2:hi), ksrc = k&1023, from W_hh[j][ksrc]
// ---------------------------------------------------------------------------
__global__ void prep_wfrag_kernel(const float* __restrict__ W_hh) {
    int wb = blockIdx.x;                   // 0..127
    int ntile = wb >> 2, warpN = wb & 3;
    uint32_t* out = (uint32_t*)g_Wfrag + (size_t)wb * 49152;
    for (int v = threadIdx.x; v < 49152; v += blockDim.x) {
        int reg   = v & 7;
        int lane  = (v >> 3) & 31;
        int kts   = v >> 8;                // 0..191
        int nb = reg >> 1, half = reg & 1;
        int unit = ntile * 32 + warpN * 8 + (lane >> 2);
        int j = (nb << 10) + unit;
        int kbase = kts * 16 + half * 8 + (lane & 3) * 2;
        uint32_t pack = 0;
#pragma unroll
        for (int i = 0; i < 2; i++) {
            int k = kbase + i;
            int seg = k >> 10, ksrc = k & 1023;
            float val = W_hh[(size_t)j * HID + ksrc];
            __nv_bfloat16 hi = __float2bfloat16(val);
            __nv_bfloat16 o = (seg == 1)
                ? __float2bfloat16(val - __bfloat162float(hi)) : hi;
            unsigned short us;
            memcpy(&us, &o, 2);
            pack |= (uint32_t)us << (16 * i);
        }
        out[v] = pack;
    }
}

// ---------------------------------------------------------------------------
// Prep 3: h0 -> A'(step 0) = [hi | hi | lo]
// ---------------------------------------------------------------------------
__global__ void init_h0_kernel(const float* __restrict__ h0) {
    int v = blockIdx.x * blockDim.x + threadIdx.x;
    int e = v * 4;
    int b = e >> 10, k = e & 1023;
    float4 h = *(const float4*)(h0 + e);
    float vv[4] = {h.x, h.y, h.z, h.w};
    union { __nv_bfloat16 b[4]; uint2 u2; } phi, plo;
#pragma unroll
    for (int x = 0; x < 4; x++) {
        __nv_bfloat16 hi = __float2bfloat16(vv[x]);
        phi.b[x] = hi;
        plo.b[x] = __float2bfloat16(vv[x] - __bfloat162float(hi));
    }
    __nv_bfloat16* row = g_A0 + (size_t)b * K3;
    *(uint2*)(row + k)        = phi.u2;
    *(uint2*)(row + 1024 + k) = phi.u2;
    *(uint2*)(row + 2048 + k) = plo.u2;
}

// ---------------------------------------------------------------------------
// Fused LSTM step: 128x128 HMMA GEMM over K'=3072 + in-register cell update.
// R4 geometry (8 warps, 2Mx4N, warp tile 64x32, CHUNK=32, NSTAGE=4) but
// B comes straight from gmem in fragment order (no SMEM for B).
// ---------------------------------------------------------------------------
__global__ __launch_bounds__(256, 2) void lstm_step_kernel(
    const __nv_bfloat16* __restrict__ Acur,
    __nv_bfloat16* __restrict__ Anext,
    const float* __restrict__ obs_t,
    float* __restrict__ hout) {
    extern __shared__ __align__(128) char dyn[];
    const int tid = threadIdx.x;
    const int wid = tid >> 5, lane = tid & 31;
    const int warpM = wid >> 2, warpN = wid & 3;   // 2 x 4 warp grid
    const int bRow = blockIdx.x * TILE_M;

    const uint32_t base = smem_u32(dyn);

    // A ldmatrix per-thread address: rows (g&1)*8+jj of warp's 64, 16B half g>>1
    const int g = lane >> 3, jj = lane & 7;
    const uint32_t aoff = (uint32_t)((warpM * 64 + ((g & 1) << 3) + jj) * ROWB
                                     + ((g >> 1) << 4));

    float acc[4][4][4];
#pragma unroll
    for (int m = 0; m < 4; m++)
#pragma unroll
        for (int n = 0; n < 4; n++)
#pragma unroll
            for (int x = 0; x < 4; x++) acc[m][n][x] = 0.f;

    // A loader: thread covers 32B of row lr at col half lc
    const int lr = tid >> 1;
    const int lc = (tid & 1) * 2;
    const __nv_bfloat16* asrc = Acur + (size_t)(bRow + lr) * K3 + lc * 8;
    const uint32_t adst = base + lr * ROWB + lc * 16;

    // B fragment stream pointer: advances 64 uint4 (1KB) per kt-step
    const uint4* bp = g_Wfrag
        + ((size_t)(blockIdx.y * 4 + warpN) * 192 * 32 + lane) * 2;

    // Preload B for kt-step 0
    uint32_t bR[2][8];
    {
        uint4 t0 = bp[0], t1 = bp[1];
        bp += 64;
        bR[0][0] = t0.x; bR[0][1] = t0.y; bR[0][2] = t0.z; bR[0][3] = t0.w;
        bR[0][4] = t1.x; bR[0][5] = t1.y; bR[0][6] = t1.z; bR[0][7] = t1.w;
    }

    // Prologue: A chunks 0..2 into stages 0..2
#pragma unroll
    for (int s = 0; s < NSTAGE - 1; s++) {
        uint32_t so = s * STAGE_BYTES;
        int k0 = s * CHUNK;
        cp16(adst + so, asrc + k0);
        cp16(adst + so + 16, asrc + k0 + 8);
        asm volatile("cp.async.commit_group;" ::: "memory");
    }

#pragma unroll 4
    for (int it = 0; it < NCHUNK; ++it) {
        asm volatile("cp.async.wait_group 2;" ::: "memory");
        __syncthreads();
        const uint32_t so = (uint32_t)(it & (NSTAGE - 1)) * STAGE_BYTES;

        // Prefetch A chunk it+3
        {
            int nl = it + NSTAGE - 1;
            if (nl < NCHUNK) {
                uint32_t so2 = (uint32_t)(nl & (NSTAGE - 1)) * STAGE_BYTES;
                int k0 = nl * CHUNK;
                cp16(adst + so2, asrc + k0);
                cp16(adst + so2 + 16, asrc + k0 + 8);
            }
            asm volatile("cp.async.commit_group;" ::: "memory");
        }

#pragma unroll
        for (int kt = 0; kt < 2; kt++) {
            const int cur = (it * 2 + kt) & 1, nxt = cur ^ 1;

            // Prefetch next kt-step's B fragments (1KB/warp, L2-resident).
            // Padding at the end of g_Wfrag covers the final over-read.
            uint4 t0 = bp[0], t1 = bp[1];
            bp += 64;

            // A fragments for this kt
            uint32_t aF[4][4];
            const uint32_t aA = base + so + aoff + kt * 32;
#pragma unroll
            for (int m = 0; m < 4; m++) ldsm4(aF[m], aA + m * 16 * ROWB);

#pragma unroll
            for (int m = 0; m < 4; m++)
#pragma unroll
                for (int n = 0; n < 4; n++)
                    mma16816(acc[m][n], aF[m], bR[cur][n * 2], bR[cur][n * 2 + 1]);

            bR[nxt][0] = t0.x; bR[nxt][1] = t0.y; bR[nxt][2] = t0.z; bR[nxt][3] = t0.w;
            bR[nxt][4] = t1.x; bR[nxt][5] = t1.y; bR[nxt][6] = t1.z; bR[nxt][7] = t1.w;
        }
    }

    // ------------------ fused LSTM epilogue (all in registers) ------------------
    const int q = lane & 3;
    const int u0 = blockIdx.y * 32 + warpN * 8 + 2 * q;    // 2 units: u0, u0+1
    const int rbase = bRow + warpM * 64 + (lane >> 2);

    float wcx[2][4], wcy[2][4], bcv[2][4];
#pragma unroll
    for (int i = 0; i < 2; i++)
#pragma unroll
        for (int gg = 0; gg < 4; gg++) {
            int j = (gg << 10) + u0 + i;
            float2 w = *(const float2*)(g_Wc + j * 2);
            wcx[i][gg] = w.x; wcy[i][gg] = w.y; bcv[i][gg] = g_bc[j];
        }

#pragma unroll
    for (int m = 0; m < 4; m++)
#pragma unroll
        for (int s = 0; s < 2; s++) {
            int b = rbase + m * 16 + s * 8;
            float2 ob = *(const float2*)(obs_t + b * 2);
            float* crow = g_cbuf + (size_t)b * HID;
            float2 cold = *(const float2*)(crow + u0);
            float cprev[2] = {cold.x, cold.y};
            float cn[2], hn[2];
#pragma unroll
            for (int i = 0; i < 2; i++) {
                float gv[4];
#pragma unroll
                for (int gg = 0; gg < 4; gg++)
                    gv[gg] = acc[m][gg][s * 2 + i]
                           + ob.x * wcx[i][gg] + ob.y * wcy[i][gg] + bcv[i][gg];
                float ig = sigm(gv[0]);
                float fg = sigm(gv[1]);
                float gc = tanh_f(gv[2]);
                float og = sigm(gv[3]);
                cn[i] = fg * cprev[i] + ig * gc;
                hn[i] = og * tanh_f(cn[i]);
            }
            *(float2*)(crow + u0) = make_float2(cn[0], cn[1]);
            if (hout)
                *(float2*)(hout + (size_t)b * HID + u0) = make_float2(hn[0], hn[1]);

            union { __nv_bfloat16 h[2]; uint32_t u; } phi, plo;
#pragma unroll
            for (int i = 0; i < 2; i++) {
                __nv_bfloat16 hi = __float2bfloat16(hn[i]);
                phi.h[i] = hi;
                plo.h[i] = __float2bfloat16(hn[i] - __bfloat162float(hi));
            }
            __nv_bfloat16* ar = Anext + (size_t)b * K3 + u0;
            *(uint32_t*)(ar)        = phi.u;
            *(uint32_t*)(ar + 1024) = phi.u;
            *(uint32_t*)(ar + 2048) = plo.u;
        }
}

// ---------------------------------------------------------------------------
extern "C" void kernel_launch(void* const* d_in, const int* in_sizes, int n_in,
                              void* d_out, int out_size) {
    const float* obs   = (const float*)d_in[0];
    const float* h0    = (const float*)d_in[1];
    const float* c0    = (const float*)d_in[2];
    const float* W_emb = (const float*)d_in[3];
    const float* b_emb = (const float*)d_in[4];
    const float* W_ih  = (const float*)d_in[5];
    const float* W_hh  = (const float*)d_in[6];
    const float* b_ih  = (const float*)d_in[7];
    const float* b_hh  = (const float*)d_in[8];

    float* cbuf;
    __nv_bfloat16 *a0, *a1;
    cudaGetSymbolAddress((void**)&cbuf, g_cbuf);
    cudaGetSymbolAddress((void**)&a0, g_A0);
    cudaGetSymbolAddress((void**)&a1, g_A1);

    cudaMemcpyAsync(cbuf, c0, sizeof(float) * BATCH * HID,
                    cudaMemcpyDeviceToDevice, 0);

    prep_wc_kernel<<<512, 256>>>(W_emb, b_emb, W_ih, b_ih, b_hh);
    prep_wfrag_kernel<<<128, 256>>>(W_hh);
    init_h0_kernel<<<BATCH * HID / 4 / 256, 256>>>(h0);

    cudaFuncSetAttribute(lstm_step_kernel,
                         cudaFuncAttributeMaxDynamicSharedMemorySize, SMEM_DYN);

    dim3 grid(BATCH / TILE_M, HID / 32);   // (16, 32)
    __nv_bfloat16* bufs[2] = {a0, a1};
    for (int t = 0; t < OBS_LEN; t++) {
        lstm_step_kernel<<<grid, 256, SMEM_DYN>>>(
            bufs[t & 1], bufs[(t + 1) & 1],
            obs + (size_t)t * BATCH * 2,
            (t == OBS_LEN - 1) ? (float*)d_out : nullptr);
    }
}

// round 9
// speedup vs baseline: 2.4512x; 1.4618x over previous
#include <cuda_runtime.h>
#include <cuda_fp16.h>
#include <math.h>
#include <stdint.h>
#include <string.h>

#define OBS_LEN 20
#define BATCH   2048
#define IN_DIM  512
#define HID     1024
#define G4      4096
#define K2      2048          // 2*HID: A' = [h_hi | h_lo], B' = [W_hi | W_hi]
#define CHUNK   32            // K per pipeline chunk
#define NCHUNK  64            // K2/CHUNK
#define TILE_M  128
#define ROWB    80            // A smem row stride (64 data + 16 pad)
#define STAGE_BYTES (128 * ROWB)          // A-only stage: 10240
#define NSTAGE  4
#define SMEM_DYN (NSTAGE * STAGE_BYTES)   // 40960

// ---------------------------------------------------------------------------
// Device scratch
// ---------------------------------------------------------------------------
__device__ __align__(16) float   g_Wc[G4 * 2];
__device__ __align__(16) float   g_bc[G4];
// B in mma-fragment order: [wb=ntile*4+warpN][ktstep=0..127][lane][8 regs]
// + 64 uint4 padding (one extra kt-step) for the tail prefetch.
#define WFRAG_U4 ((size_t)128 * 128 * 32 * 2 + 64)
__device__ __align__(16) uint4   g_Wfrag[WFRAG_U4];          // ~16.8 MB
__device__ __align__(16) __half  g_A0[(size_t)BATCH * K2];   // 8.4 MB
__device__ __align__(16) __half  g_A1[(size_t)BATCH * K2];
__device__ __align__(16) float   g_cbuf[(size_t)BATCH * HID];

// ---------------------------------------------------------------------------
// Helpers (family-portable PTX only: cp.async / ldmatrix / mma.sync)
// ---------------------------------------------------------------------------
__device__ __forceinline__ uint32_t smem_u32(const void* p) {
    uint32_t a;
    asm("{ .reg .u64 t; cvta.to.shared.u64 t, %1; cvt.u32.u64 %0, t; }"
        : "=r"(a) : "l"(p));
    return a;
}
__device__ __forceinline__ void cp16(uint32_t dst, const void* src) {
    asm volatile("cp.async.cg.shared.global [%0], [%1], 16;"
                 :: "r"(dst), "l"(src) : "memory");
}
__device__ __forceinline__ void ldsm4(uint32_t* r, uint32_t addr) {
    asm volatile("ldmatrix.sync.aligned.m8n8.x4.shared.b16 {%0,%1,%2,%3}, [%4];"
                 : "=r"(r[0]), "=r"(r[1]), "=r"(r[2]), "=r"(r[3]) : "r"(addr));
}
__device__ __forceinline__ void mma16816(float* d, const uint32_t* a,
                                         uint32_t b0, uint32_t b1) {
    asm volatile(
        "mma.sync.aligned.m16n8k16.row.col.f32.f16.f16.f32 "
        "{%0,%1,%2,%3},{%4,%5,%6,%7},{%8,%9},{%0,%1,%2,%3};"
        : "+f"(d[0]), "+f"(d[1]), "+f"(d[2]), "+f"(d[3])
        : "r"(a[0]), "r"(a[1]), "r"(a[2]), "r"(a[3]), "r"(b0), "r"(b1));
}
__device__ __forceinline__ float sigm(float x) {
    return __fdividef(1.f, 1.f + __expf(-x));
}
__device__ __forceinline__ float tanh_f(float x) {
    return __fdividef(2.f, 1.f + __expf(-2.f * x)) - 1.f;
}

// ---------------------------------------------------------------------------
// Prep 1: fold embedding into per-gate input weights (Wc [G4][2], bc [G4]).
// ---------------------------------------------------------------------------
__global__ void prep_wc_kernel(const float* __restrict__ W_emb,
                               const float* __restrict__ b_emb,
                               const float* __restrict__ W_ih,
                               const float* __restrict__ b_ih,
                               const float* __restrict__ b_hh) {
    int warp = (blockIdx.x * blockDim.x + threadIdx.x) >> 5;
    int lane = threadIdx.x & 31;
    if (warp >= G4) return;
    const float* wrow = W_ih + (size_t)warp * IN_DIM;
    float s0 = 0.f, s1 = 0.f, sb = 0.f;
    for (int h = lane; h < IN_DIM; h += 32) {
        float w = wrow[h];
        s0 += w * W_emb[h * 2 + 0];
        s1 += w * W_emb[h * 2 + 1];
        sb += w * b_emb[h];
    }
#pragma unroll
    for (int o = 16; o > 0; o >>= 1) {
        s0 += __shfl_down_sync(0xffffffffu, s0, o);
        s1 += __shfl_down_sync(0xffffffffu, s1, o);
        sb += __shfl_down_sync(0xffffffffu, sb, o);
    }
    if (lane == 0) {
        g_Wc[warp * 2 + 0] = s0;
        g_Wc[warp * 2 + 1] = s1;
        g_bc[warp] = sb + b_ih[warp] + b_hh[warp];
    }
}

// ---------------------------------------------------------------------------
// Prep 2: build B' = [W_hi | W_hi] (fp16) in exact mma b-fragment order.
// For wb = ntile*4+warpN, ktstep = 0..127, lane, reg = nb*2+half:
//   gate = nb ; unit = ntile*32 + warpN*8 + (lane>>2) ; j = gate*1024+unit
//   k    = ktstep*16 + half*8 + (lane&3)*2 + i   (i = 0,1 packed in uint32)
//   ksrc = k & 1023 (K segment duplicated), value = fp16(W_hh[j][ksrc])
// ---------------------------------------------------------------------------
__global__ void prep_wfrag_kernel(const float* __restrict__ W_hh) {
    int wb = blockIdx.x;                   // 0..127
    int ntile = wb >> 2, warpN = wb & 3;
    uint32_t* out = (uint32_t*)g_Wfrag + (size_t)wb * 32768;
    for (int v = threadIdx.x; v < 32768; v += blockDim.x) {
        int reg   = v & 7;
        int lane  = (v >> 3) & 31;
        int kts   = v >> 8;                // 0..127
        int nb = reg >> 1, half = reg & 1;
        int unit = ntile * 32 + warpN * 8 + (lane >> 2);
        int j = (nb << 10) + unit;
        int kbase = kts * 16 + half * 8 + (lane & 3) * 2;
        uint32_t pack = 0;
#pragma unroll
        for (int i = 0; i < 2; i++) {
            int ksrc = (kbase + i) & 1023;
            __half o = __float2half(W_hh[(size_t)j * HID + ksrc]);
            unsigned short us;
            memcpy(&us, &o, 2);
            pack |= (uint32_t)us << (16 * i);
        }
        out[v] = pack;
    }
}

// ---------------------------------------------------------------------------
// Prep 3: h0 -> A'(step 0) = [h_hi | h_lo] (fp16 two-term split)
// ---------------------------------------------------------------------------
__global__ void init_h0_kernel(const float* __restrict__ h0) {
    int v = blockIdx.x * blockDim.x + threadIdx.x;
    int e = v * 4;
    int b = e >> 10, k = e & 1023;
    float4 h = *(const float4*)(h0 + e);
    float vv[4] = {h.x, h.y, h.z, h.w};
    union { __half b[4]; uint2 u2; } phi, plo;
#pragma unroll
    for (int x = 0; x < 4; x++) {
        __half hi = __float2half(vv[x]);
        phi.b[x] = hi;
        plo.b[x] = __float2half(vv[x] - __half2float(hi));
    }
    __half* row = g_A0 + (size_t)b * K2;
    *(uint2*)(row + k)        = phi.u2;
    *(uint2*)(row + 1024 + k) = plo.u2;
}

// ---------------------------------------------------------------------------
// Fused LSTM step: 128x128 HMMA GEMM over K'=2048 + in-register cell update.
// R8 schedule (8 warps, 2Mx4N, warp tile 64x32, CHUNK=32, NSTAGE=4),
// B streamed from gmem in fragment order, fp16 2-term arithmetic.
// ---------------------------------------------------------------------------
__global__ __launch_bounds__(256, 2) void lstm_step_kernel(
    const __half* __restrict__ Acur,
    __half* __restrict__ Anext,
    const float* __restrict__ obs_t,
    float* __restrict__ hout) {
    extern __shared__ __align__(128) char dyn[];
    const int tid = threadIdx.x;
    const int wid = tid >> 5, lane = tid & 31;
    const int warpM = wid >> 2, warpN = wid & 3;   // 2 x 4 warp grid
    const int bRow = blockIdx.x * TILE_M;

    const uint32_t base = smem_u32(dyn);

    // A ldmatrix per-thread address: rows (g&1)*8+jj of warp's 64, 16B half g>>1
    const int g = lane >> 3, jj = lane & 7;
    const uint32_t aoff = (uint32_t)((warpM * 64 + ((g & 1) << 3) + jj) * ROWB
                                     + ((g >> 1) << 4));

    float acc[4][4][4];
#pragma unroll
    for (int m = 0; m < 4; m++)
#pragma unroll
        for (int n = 0; n < 4; n++)
#pragma unroll
            for (int x = 0; x < 4; x++) acc[m][n][x] = 0.f;

    // A loader: thread covers 32B of row lr at col half lc
    const int lr = tid >> 1;
    const int lc = (tid & 1) * 2;
    const __half* asrc = Acur + (size_t)(bRow + lr) * K2 + lc * 8;
    const uint32_t adst = base + lr * ROWB + lc * 16;

    // B fragment stream pointer: advances 64 uint4 (1KB) per kt-step
    const uint4* bp = g_Wfrag
        + ((size_t)(blockIdx.y * 4 + warpN) * 128 * 32 + lane) * 2;

    // Preload B for kt-step 0
    uint32_t bR[2][8];
    {
        uint4 t0 = bp[0], t1 = bp[1];
        bp += 64;
        bR[0][0] = t0.x; bR[0][1] = t0.y; bR[0][2] = t0.z; bR[0][3] = t0.w;
        bR[0][4] = t1.x; bR[0][5] = t1.y; bR[0][6] = t1.z; bR[0][7] = t1.w;
    }

    // Prologue: A chunks 0..2 into stages 0..2
#pragma unroll
    for (int s = 0; s < NSTAGE - 1; s++) {
        uint32_t so = s * STAGE_BYTES;
        int k0 = s * CHUNK;
        cp16(adst + so, asrc + k0);
        cp16(adst + so + 16, asrc + k0 + 8);
        asm volatile("cp.async.commit_group;" ::: "memory");
    }

#pragma unroll 4
    for (int it = 0; it < NCHUNK; ++it) {
        asm volatile("cp.async.wait_group 2;" ::: "memory");
        __syncthreads();
        const uint32_t so = (uint32_t)(it & (NSTAGE - 1)) * STAGE_BYTES;

        // Prefetch A chunk it+3
        {
            int nl = it + NSTAGE - 1;
            if (nl < NCHUNK) {
                uint32_t so2 = (uint32_t)(nl & (NSTAGE - 1)) * STAGE_BYTES;
                int k0 = nl * CHUNK;
                cp16(adst + so2, asrc + k0);
                cp16(adst + so2 + 16, asrc + k0 + 8);
            }
            asm volatile("cp.async.commit_group;" ::: "memory");
        }

#pragma unroll
        for (int kt = 0; kt < 2; kt++) {
            const int cur = (it * 2 + kt) & 1, nxt = cur ^ 1;

            // Prefetch next kt-step's B fragments (1KB/warp, L2-resident).
            // Padding at the end of g_Wfrag covers the final over-read.
            uint4 t0 = bp[0], t1 = bp[1];
            bp += 64;

            // A fragments for this kt
            uint32_t aF[4][4];
            const uint32_t aA = base + so + aoff + kt * 32;
#pragma unroll
            for (int m = 0; m < 4; m++) ldsm4(aF[m], aA + m * 16 * ROWB);

#pragma unroll
            for (int m = 0; m < 4; m++)
#pragma unroll
                for (int n = 0; n < 4; n++)
                    mma16816(acc[m][n], aF[m], bR[cur][n * 2], bR[cur][n * 2 + 1]);

            bR[nxt][0] = t0.x; bR[nxt][1] = t0.y; bR[nxt][2] = t0.z; bR[nxt][3] = t0.w;
            bR[nxt][4] = t1.x; bR[nxt][5] = t1.y; bR[nxt][6] = t1.z; bR[nxt][7] = t1.w;
        }
    }

    // ------------------ fused LSTM epilogue (all in registers) ------------------
    const int q = lane & 3;
    const int u0 = blockIdx.y * 32 + warpN * 8 + 2 * q;    // 2 units: u0, u0+1
    const int rbase = bRow + warpM * 64 + (lane >> 2);

    float wcx[2][4], wcy[2][4], bcv[2][4];
#pragma unroll
    for (int i = 0; i < 2; i++)
#pragma unroll
        for (int gg = 0; gg < 4; gg++) {
            int j = (gg << 10) + u0 + i;
            float2 w = *(const float2*)(g_Wc + j * 2);
            wcx[i][gg] = w.x; wcy[i][gg] = w.y; bcv[i][gg] = g_bc[j];
        }

#pragma unroll
    for (int m = 0; m < 4; m++)
#pragma unroll
        for (int s = 0; s < 2; s++) {
            int b = rbase + m * 16 + s * 8;
            float2 ob = *(const float2*)(obs_t + b * 2);
            float* crow = g_cbuf + (size_t)b * HID;
            float2 cold = *(const float2*)(crow + u0);
            float cprev[2] = {cold.x, cold.y};
            float cn[2], hn[2];
#pragma unroll
            for (int i = 0; i < 2; i++) {
                float gv[4];
#pragma unroll
                for (int gg = 0; gg < 4; gg++)
                    gv[gg] = acc[m][gg][s * 2 + i]
                           + ob.x * wcx[i][gg] + ob.y * wcy[i][gg] + bcv[i][gg];
                float ig = sigm(gv[0]);
                float fg = sigm(gv[1]);
                float gc = tanh_f(gv[2]);
                float og = sigm(gv[3]);
                cn[i] = fg * cprev[i] + ig * gc;
                hn[i] = og * tanh_f(cn[i]);
            }
            *(float2*)(crow + u0) = make_float2(cn[0], cn[1]);
            if (hout)
                *(float2*)(hout + (size_t)b * HID + u0) = make_float2(hn[0], hn[1]);

            union { __half h[2]; uint32_t u; } phi, plo;
#pragma unroll
            for (int i = 0; i < 2; i++) {
                __half hi = __float2half(hn[i]);
                phi.h[i] = hi;
                plo.h[i] = __float2half(hn[i] - __half2float(hi));
            }
            __half* ar = Anext + (size_t)b * K2 + u0;
            *(uint32_t*)(ar)        = phi.u;
            *(uint32_t*)(ar + 1024) = plo.u;
        }
}

// ---------------------------------------------------------------------------
extern "C" void kernel_launch(void* const* d_in, const int* in_sizes, int n_in,
                              void* d_out, int out_size) {
    const float* obs   = (const float*)d_in[0];
    const float* h0    = (const float*)d_in[1];
    const float* c0    = (const float*)d_in[2];
    const float* W_emb = (const float*)d_in[3];
    const float* b_emb = (const float*)d_in[4];
    const float* W_ih  = (const float*)d_in[5];
    const float* W_hh  = (const float*)d_in[6];
    const float* b_ih  = (const float*)d_in[7];
    const float* b_hh  = (const float*)d_in[8];

    float* cbuf;
    __half *a0, *a1;
    cudaGetSymbolAddress((void**)&cbuf, g_cbuf);
    cudaGetSymbolAddress((void**)&a0, g_A0);
    cudaGetSymbolAddress((void**)&a1, g_A1);

    cudaMemcpyAsync(cbuf, c0, sizeof(float) * BATCH * HID,
                    cudaMemcpyDeviceToDevice, 0);

    prep_wc_kernel<<<512, 256>>>(W_emb, b_emb, W_ih, b_ih, b_hh);
    prep_wfrag_kernel<<<128, 256>>>(W_hh);
    init_h0_kernel<<<BATCH * HID / 4 / 256, 256>>>(h0);

    cudaFuncSetAttribute(lstm_step_kernel,
                         cudaFuncAttributeMaxDynamicSharedMemorySize, SMEM_DYN);

    dim3 grid(BATCH / TILE_M, HID / 32);   // (16, 32)
    __half* bufs[2] = {a0, a1};
    for (int t = 0; t < OBS_LEN; t++) {
        lstm_step_kernel<<<grid, 256, SMEM_DYN>>>(
            bufs[t & 1], bufs[(t + 1) & 1],
            obs + (size_t)t * BATCH * 2,
            (t == OBS_LEN - 1) ? (float*)d_out : nullptr);
    }
}

// round 10
// speedup vs baseline: 4.5105x; 1.8401x over previous
#include <cuda_runtime.h>
#include <cuda_fp16.h>
#include <math.h>
#include <stdint.h>
#include <string.h>

#define OBS_LEN 20
#define BATCH   2048
#define IN_DIM  512
#define HID     1024
#define G4      4096
#define K1      1024          // single-pass fp16: A' = fp16(h), B' = fp16(W)
#define CHUNK   32            // K per pipeline chunk
#define NCHUNK  32            // K1/CHUNK
#define TILE_M  128
#define ROWB    80            // A smem row stride (64 data + 16 pad)
#define STAGE_BYTES (128 * ROWB)          // A-only stage: 10240
#define NSTAGE  4
#define SMEM_DYN (NSTAGE * STAGE_BYTES)   // 40960

// ---------------------------------------------------------------------------
// Device scratch
// ---------------------------------------------------------------------------
__device__ __align__(16) float   g_Wc[G4 * 2];
__device__ __align__(16) float   g_bc[G4];
// B in mma-fragment order: [wb=ntile*4+warpN][ktstep=0..63][lane][8 regs]
// + 64 uint4 padding (one extra kt-step) for the tail prefetch.
#define WFRAG_U4 ((size_t)128 * 64 * 32 * 2 + 64)
__device__ __align__(16) uint4   g_Wfrag[WFRAG_U4];          // ~8.4 MB
__device__ __align__(16) __half  g_A0[(size_t)BATCH * K1];   // 4.2 MB
__device__ __align__(16) __half  g_A1[(size_t)BATCH * K1];
__device__ __align__(16) float   g_cbuf[(size_t)BATCH * HID];

// ---------------------------------------------------------------------------
// Helpers (family-portable PTX only: cp.async / ldmatrix / mma.sync)
// ---------------------------------------------------------------------------
__device__ __forceinline__ uint32_t smem_u32(const void* p) {
    uint32_t a;
    asm("{ .reg .u64 t; cvta.to.shared.u64 t, %1; cvt.u32.u64 %0, t; }"
        : "=r"(a) : "l"(p));
    return a;
}
__device__ __forceinline__ void cp16(uint32_t dst, const void* src) {
    asm volatile("cp.async.cg.shared.global [%0], [%1], 16;"
                 :: "r"(dst), "l"(src) : "memory");
}
__device__ __forceinline__ void ldsm4(uint32_t* r, uint32_t addr) {
    asm volatile("ldmatrix.sync.aligned.m8n8.x4.shared.b16 {%0,%1,%2,%3}, [%4];"
                 : "=r"(r[0]), "=r"(r[1]), "=r"(r[2]), "=r"(r[3]) : "r"(addr));
}
__device__ __forceinline__ void mma16816(float* d, const uint32_t* a,
                                         uint32_t b0, uint32_t b1) {
    asm volatile(
        "mma.sync.aligned.m16n8k16.row.col.f32.f16.f16.f32 "
        "{%0,%1,%2,%3},{%4,%5,%6,%7},{%8,%9},{%0,%1,%2,%3};"
        : "+f"(d[0]), "+f"(d[1]), "+f"(d[2]), "+f"(d[3])
        : "r"(a[0]), "r"(a[1]), "r"(a[2]), "r"(a[3]), "r"(b0), "r"(b1));
}
__device__ __forceinline__ float sigm(float x) {
    return __fdividef(1.f, 1.f + __expf(-x));
}
__device__ __forceinline__ float tanh_f(float x) {
    return __fdividef(2.f, 1.f + __expf(-2.f * x)) - 1.f;
}

// ---------------------------------------------------------------------------
// Prep 1: fold embedding into per-gate input weights (Wc [G4][2], bc [G4]).
// ---------------------------------------------------------------------------
__global__ void prep_wc_kernel(const float* __restrict__ W_emb,
                               const float* __restrict__ b_emb,
                               const float* __restrict__ W_ih,
                               const float* __restrict__ b_ih,
                               const float* __restrict__ b_hh) {
    int warp = (blockIdx.x * blockDim.x + threadIdx.x) >> 5;
    int lane = threadIdx.x & 31;
    if (warp >= G4) return;
    const float* wrow = W_ih + (size_t)warp * IN_DIM;
    float s0 = 0.f, s1 = 0.f, sb = 0.f;
    for (int h = lane; h < IN_DIM; h += 32) {
        float w = wrow[h];
        s0 += w * W_emb[h * 2 + 0];
        s1 += w * W_emb[h * 2 + 1];
        sb += w * b_emb[h];
    }
#pragma unroll
    for (int o = 16; o > 0; o >>= 1) {
        s0 += __shfl_down_sync(0xffffffffu, s0, o);
        s1 += __shfl_down_sync(0xffffffffu, s1, o);
        sb += __shfl_down_sync(0xffffffffu, sb, o);
    }
    if (lane == 0) {
        g_Wc[warp * 2 + 0] = s0;
        g_Wc[warp * 2 + 1] = s1;
        g_bc[warp] = sb + b_ih[warp] + b_hh[warp];
    }
}

// ---------------------------------------------------------------------------
// Prep 2: build B' = fp16(W_hh) in exact mma b-fragment order.
// For wb = ntile*4+warpN, ktstep = 0..63, lane, reg = nb*2+half:
//   gate = nb ; unit = ntile*32 + warpN*8 + (lane>>2) ; j = gate*1024+unit
//   k    = ktstep*16 + half*8 + (lane&3)*2 + i   (i = 0,1 packed in uint32)
// ---------------------------------------------------------------------------
__global__ void prep_wfrag_kernel(const float* __restrict__ W_hh) {
    int wb = blockIdx.x;                   // 0..127
    int ntile = wb >> 2, warpN = wb & 3;
    uint32_t* out = (uint32_t*)g_Wfrag + (size_t)wb * 16384;
    for (int v = threadIdx.x; v < 16384; v += blockDim.x) {
        int reg   = v & 7;
        int lane  = (v >> 3) & 31;
        int kts   = v >> 8;                // 0..63
        int nb = reg >> 1, half = reg & 1;
        int unit = ntile * 32 + warpN * 8 + (lane >> 2);
        int j = (nb << 10) + unit;
        int kbase = kts * 16 + half * 8 + (lane & 3) * 2;
        uint32_t pack = 0;
#pragma unroll
        for (int i = 0; i < 2; i++) {
            __half o = __float2half(W_hh[(size_t)j * HID + kbase + i]);
            unsigned short us;
            memcpy(&us, &o, 2);
            pack |= (uint32_t)us << (16 * i);
        }
        out[v] = pack;
    }
}

// ---------------------------------------------------------------------------
// Prep 3: h0 -> A'(step 0) = fp16(h0)
// ---------------------------------------------------------------------------
__global__ void init_h0_kernel(const float* __restrict__ h0) {
    int v = blockIdx.x * blockDim.x + threadIdx.x;
    int e = v * 4;
    float4 h = *(const float4*)(h0 + e);
    float vv[4] = {h.x, h.y, h.z, h.w};
    union { __half b[4]; uint2 u2; } phi;
#pragma unroll
    for (int x = 0; x < 4; x++) phi.b[x] = __float2half(vv[x]);
    *(uint2*)(g_A0 + e) = phi.u2;
}

// ---------------------------------------------------------------------------
// Fused LSTM step: 128x128 HMMA GEMM over K=1024 + in-register cell update.
// 8 warps (2Mx4N, warp tile 64x32), CHUNK=32, NSTAGE=4, B streamed from
// gmem in fragment order, single-pass fp16.
// ---------------------------------------------------------------------------
__global__ __launch_bounds__(256, 2) void lstm_step_kernel(
    const __half* __restrict__ Acur,
    __half* __restrict__ Anext,
    const float* __restrict__ obs_t,
    float* __restrict__ hout) {
    extern __shared__ __align__(128) char dyn[];
    const int tid = threadIdx.x;
    const int wid = tid >> 5, lane = tid & 31;
    const int warpM = wid >> 2, warpN = wid & 3;   // 2 x 4 warp grid
    const int bRow = blockIdx.x * TILE_M;

    const uint32_t base = smem_u32(dyn);

    // A ldmatrix per-thread address: rows (g&1)*8+jj of warp's 64, 16B half g>>1
    const int g = lane >> 3, jj = lane & 7;
    const uint32_t aoff = (uint32_t)((warpM * 64 + ((g & 1) << 3) + jj) * ROWB
                                     + ((g >> 1) << 4));

    float acc[4][4][4];
#pragma unroll
    for (int m = 0; m < 4; m++)
#pragma unroll
        for (int n = 0; n < 4; n++)
#pragma unroll
            for (int x = 0; x < 4; x++) acc[m][n][x] = 0.f;

    // A loader: thread covers 32B of row lr at col half lc
    const int lr = tid >> 1;
    const int lc = (tid & 1) * 2;
    const __half* asrc = Acur + (size_t)(bRow + lr) * K1 + lc * 8;
    const uint32_t adst = base + lr * ROWB + lc * 16;

    // B fragment stream pointer: advances 64 uint4 (1KB) per kt-step
    const uint4* bp = g_Wfrag
        + ((size_t)(blockIdx.y * 4 + warpN) * 64 * 32 + lane) * 2;

    // Preload B for kt-step 0
    uint32_t bR[2][8];
    {
        uint4 t0 = bp[0], t1 = bp[1];
        bp += 64;
        bR[0][0] = t0.x; bR[0][1] = t0.y; bR[0][2] = t0.z; bR[0][3] = t0.w;
        bR[0][4] = t1.x; bR[0][5] = t1.y; bR[0][6] = t1.z; bR[0][7] = t1.w;
    }

    // Prologue: A chunks 0..2 into stages 0..2
#pragma unroll
    for (int s = 0; s < NSTAGE - 1; s++) {
        uint32_t so = s * STAGE_BYTES;
        int k0 = s * CHUNK;
        cp16(adst + so, asrc + k0);
        cp16(adst + so + 16, asrc + k0 + 8);
        asm volatile("cp.async.commit_group;" ::: "memory");
    }

#pragma unroll 4
    for (int it = 0; it < NCHUNK; ++it) {
        asm volatile("cp.async.wait_group 2;" ::: "memory");
        __syncthreads();
        const uint32_t so = (uint32_t)(it & (NSTAGE - 1)) * STAGE_BYTES;

        // Prefetch A chunk it+3
        {
            int nl = it + NSTAGE - 1;
            if (nl < NCHUNK) {
                uint32_t so2 = (uint32_t)(nl & (NSTAGE - 1)) * STAGE_BYTES;
                int k0 = nl * CHUNK;
                cp16(adst + so2, asrc + k0);
                cp16(adst + so2 + 16, asrc + k0 + 8);
            }
            asm volatile("cp.async.commit_group;" ::: "memory");
        }

#pragma unroll
        for (int kt = 0; kt < 2; kt++) {
            const int cur = (it * 2 + kt) & 1, nxt = cur ^ 1;

            // Prefetch next kt-step's B fragments (1KB/warp, L2-resident).
            // Padding at the end of g_Wfrag covers the final over-read.
            uint4 t0 = bp[0], t1 = bp[1];
            bp += 64;

            // A fragments for this kt
            uint32_t aF[4][4];
            const uint32_t aA = base + so + aoff + kt * 32;
#pragma unroll
            for (int m = 0; m < 4; m++) ldsm4(aF[m], aA + m * 16 * ROWB);

#pragma unroll
            for (int m = 0; m < 4; m++)
#pragma unroll
                for (int n = 0; n < 4; n++)
                    mma16816(acc[m][n], aF[m], bR[cur][n * 2], bR[cur][n * 2 + 1]);

            bR[nxt][0] = t0.x; bR[nxt][1] = t0.y; bR[nxt][2] = t0.z; bR[nxt][3] = t0.w;
            bR[nxt][4] = t1.x; bR[nxt][5] = t1.y; bR[nxt][6] = t1.z; bR[nxt][7] = t1.w;
        }
    }

    // ------------------ fused LSTM epilogue (all in registers) ------------------
    const int q = lane & 3;
    const int u0 = blockIdx.y * 32 + warpN * 8 + 2 * q;    // 2 units: u0, u0+1
    const int rbase = bRow + warpM * 64 + (lane >> 2);

    float wcx[2][4], wcy[2][4], bcv[2][4];
#pragma unroll
    for (int i = 0; i < 2; i++)
#pragma unroll
        for (int gg = 0; gg < 4; gg++) {
            int j = (gg << 10) + u0 + i;
            float2 w = *(const float2*)(g_Wc + j * 2);
            wcx[i][gg] = w.x; wcy[i][gg] = w.y; bcv[i][gg] = g_bc[j];
        }

#pragma unroll
    for (int m = 0; m < 4; m++)
#pragma unroll
        for (int s = 0; s < 2; s++) {
            int b = rbase + m * 16 + s * 8;
            float2 ob = *(const float2*)(obs_t + b * 2);
            float* crow = g_cbuf + (size_t)b * HID;
            float2 cold = *(const float2*)(crow + u0);
            float cprev[2] = {cold.x, cold.y};
            float cn[2], hn[2];
#pragma unroll
            for (int i = 0; i < 2; i++) {
                float gv[4];
#pragma unroll
                for (int gg = 0; gg < 4; gg++)
                    gv[gg] = acc[m][gg][s * 2 + i]
                           + ob.x * wcx[i][gg] + ob.y * wcy[i][gg] + bcv[i][gg];
                float ig = sigm(gv[0]);
                float fg = sigm(gv[1]);
                float gc = tanh_f(gv[2]);
                float og = sigm(gv[3]);
                cn[i] = fg * cprev[i] + ig * gc;
                hn[i] = og * tanh_f(cn[i]);
            }
            *(float2*)(crow + u0) = make_float2(cn[0], cn[1]);
            if (hout)
                *(float2*)(hout + (size_t)b * HID + u0) = make_float2(hn[0], hn[1]);

            union { __half h[2]; uint32_t u; } phi;
#pragma unroll
            for (int i = 0; i < 2; i++) phi.h[i] = __float2half(hn[i]);
            *(uint32_t*)(Anext + (size_t)b * K1 + u0) = phi.u;
        }
}

// ---------------------------------------------------------------------------
extern "C" void kernel_launch(void* const* d_in, const int* in_sizes, int n_in,
                              void* d_out, int out_size) {
    const float* obs   = (const float*)d_in[0];
    const float* h0    = (const float*)d_in[1];
    const float* c0    = (const float*)d_in[2];
    const float* W_emb = (const float*)d_in[3];
    const float* b_emb = (const float*)d_in[4];
    const float* W_ih  = (const float*)d_in[5];
    const float* W_hh  = (const float*)d_in[6];
    const float* b_ih  = (const float*)d_in[7];
    const float* b_hh  = (const float*)d_in[8];

    float* cbuf;
    __half *a0, *a1;
    cudaGetSymbolAddress((void**)&cbuf, g_cbuf);
    cudaGetSymbolAddress((void**)&a0, g_A0);
    cudaGetSymbolAddress((void**)&a1, g_A1);

    cudaMemcpyAsync(cbuf, c0, sizeof(float) * BATCH * HID,
                    cudaMemcpyDeviceToDevice, 0);

    prep_wc_kernel<<<512, 256>>>(W_emb, b_emb, W_ih, b_ih, b_hh);
    prep_wfrag_kernel<<<128, 256>>>(W_hh);
    init_h0_kernel<<<BATCH * HID / 4 / 256, 256>>>(h0);

    cudaFuncSetAttribute(lstm_step_kernel,
                         cudaFuncAttributeMaxDynamicSharedMemorySize, SMEM_DYN);

    dim3 grid(BATCH / TILE_M, HID / 32);   // (16, 32)
    __half* bufs[2] = {a0, a1};
    for (int t = 0; t < OBS_LEN; t++) {
        lstm_step_kernel<<<grid, 256, SMEM_DYN>>>(
            bufs[t & 1], bufs[(t + 1) & 1],
            obs + (size_t)t * BATCH * 2,
            (t == OBS_LEN - 1) ? (float*)d_out : nullptr);
    }
}

// round 11
// speedup vs baseline: 4.5863x; 1.0168x over previous
#include <cuda_runtime.h>
#include <cuda_fp16.h>
#include <math.h>
#include <stdint.h>
#include <string.h>

#define OBS_LEN 20
#define BATCH   2048
#define IN_DIM  512
#define HID     1024
#define G4      4096
#define K1      1024          // single-pass fp16: A' = fp16(h), B' = fp16(W)
#define CHUNK   32            // K per pipeline chunk
#define NCHUNK  32            // K1/CHUNK
#define TILE_M  128
#define ROWB    80            // A smem row stride (64 data + 16 pad)
#define STAGE_BYTES (128 * ROWB)          // A-only stage: 10240
#define NSTAGE  4
#define SMEM_DYN (NSTAGE * STAGE_BYTES)   // 40960

// ---------------------------------------------------------------------------
// Device scratch
// ---------------------------------------------------------------------------
__device__ __align__(16) float   g_Wc[G4 * 2];
__device__ __align__(16) float   g_bc[G4];
// B in mma-fragment order: [wb=ntile*4+warpN][ktstep=0..63][lane][8 regs]
// + 64 uint4 padding (one extra kt-step) for the tail prefetch.
#define WFRAG_U4 ((size_t)128 * 64 * 32 * 2 + 64)
__device__ __align__(16) uint4   g_Wfrag[WFRAG_U4];          // ~8.4 MB
__device__ __align__(16) __half  g_A0[(size_t)BATCH * K1];   // 4.2 MB
__device__ __align__(16) __half  g_A1[(size_t)BATCH * K1];
__device__ __align__(16) float   g_cbuf[(size_t)BATCH * HID];

// ---------------------------------------------------------------------------
// Helpers (family-portable PTX only: cp.async / ldmatrix / mma.sync)
// ---------------------------------------------------------------------------
__device__ __forceinline__ uint32_t smem_u32(const void* p) {
    uint32_t a;
    asm("{ .reg .u64 t; cvta.to.shared.u64 t, %1; cvt.u32.u64 %0, t; }"
        : "=r"(a) : "l"(p));
    return a;
}
__device__ __forceinline__ void cp16(uint32_t dst, const void* src) {
    asm volatile("cp.async.cg.shared.global [%0], [%1], 16;"
                 :: "r"(dst), "l"(src) : "memory");
}
__device__ __forceinline__ void ldsm4(uint32_t* r, uint32_t addr) {
    asm volatile("ldmatrix.sync.aligned.m8n8.x4.shared.b16 {%0,%1,%2,%3}, [%4];"
                 : "=r"(r[0]), "=r"(r[1]), "=r"(r[2]), "=r"(r[3]) : "r"(addr));
}
__device__ __forceinline__ void mma16816(float* d, const uint32_t* a,
                                         uint32_t b0, uint32_t b1) {
    asm volatile(
        "mma.sync.aligned.m16n8k16.row.col.f32.f16.f16.f32 "
        "{%0,%1,%2,%3},{%4,%5,%6,%7},{%8,%9},{%0,%1,%2,%3};"
        : "+f"(d[0]), "+f"(d[1]), "+f"(d[2]), "+f"(d[3])
        : "r"(a[0]), "r"(a[1]), "r"(a[2]), "r"(a[3]), "r"(b0), "r"(b1));
}
__device__ __forceinline__ float sigm(float x) {
    return __fdividef(1.f, 1.f + __expf(-x));
}
__device__ __forceinline__ float tanh_f(float x) {
    return __fdividef(2.f, 1.f + __expf(-2.f * x)) - 1.f;
}

// ---------------------------------------------------------------------------
// Prep 1: fold embedding into per-gate input weights (Wc [G4][2], bc [G4]).
// ---------------------------------------------------------------------------
__global__ void prep_wc_kernel(const float* __restrict__ W_emb,
                               const float* __restrict__ b_emb,
                               const float* __restrict__ W_ih,
                               const float* __restrict__ b_ih,
                               const float* __restrict__ b_hh) {
    int warp = (blockIdx.x * blockDim.x + threadIdx.x) >> 5;
    int lane = threadIdx.x & 31;
    if (warp >= G4) return;
    const float* wrow = W_ih + (size_t)warp * IN_DIM;
    float s0 = 0.f, s1 = 0.f, sb = 0.f;
    for (int h = lane; h < IN_DIM; h += 32) {
        float w = wrow[h];
        s0 += w * W_emb[h * 2 + 0];
        s1 += w * W_emb[h * 2 + 1];
        sb += w * b_emb[h];
    }
#pragma unroll
    for (int o = 16; o > 0; o >>= 1) {
        s0 += __shfl_down_sync(0xffffffffu, s0, o);
        s1 += __shfl_down_sync(0xffffffffu, s1, o);
        sb += __shfl_down_sync(0xffffffffu, sb, o);
    }
    if (lane == 0) {
        g_Wc[warp * 2 + 0] = s0;
        g_Wc[warp * 2 + 1] = s1;
        g_bc[warp] = sb + b_ih[warp] + b_hh[warp];
    }
}

// ---------------------------------------------------------------------------
// Prep 2: build B' = fp16(W_hh) in exact mma b-fragment order.
// 512 blocks: wb = blockIdx.x>>2 handles quarter (blockIdx.x&3) of v-range.
// For wb = ntile*4+warpN, ktstep = 0..63, lane, reg = nb*2+half:
//   gate = nb ; unit = ntile*32 + warpN*8 + (lane>>2) ; j = gate*1024+unit
//   k    = ktstep*16 + half*8 + (lane&3)*2 + i   (i = 0,1 packed in uint32)
// ---------------------------------------------------------------------------
__global__ void prep_wfrag_kernel(const float* __restrict__ W_hh) {
    int wb = blockIdx.x >> 2;              // 0..127
    int vbase = (blockIdx.x & 3) * 4096;   // quarter of 16384
    int ntile = wb >> 2, warpN = wb & 3;
    uint32_t* out = (uint32_t*)g_Wfrag + (size_t)wb * 16384;
    for (int v = vbase + threadIdx.x; v < vbase + 4096; v += blockDim.x) {
        int reg   = v & 7;
        int lane  = (v >> 3) & 31;
        int kts   = v >> 8;                // 0..63
        int nb = reg >> 1, half = reg & 1;
        int unit = ntile * 32 + warpN * 8 + (lane >> 2);
        int j = (nb << 10) + unit;
        int kbase = kts * 16 + half * 8 + (lane & 3) * 2;
        uint32_t pack = 0;
#pragma unroll
        for (int i = 0; i < 2; i++) {
            __half o = __float2half(W_hh[(size_t)j * HID + kbase + i]);
            unsigned short us;
            memcpy(&us, &o, 2);
            pack |= (uint32_t)us << (16 * i);
        }
        out[v] = pack;
    }
}

// ---------------------------------------------------------------------------
// Prep 3: h0 -> A'(step 0) = fp16(h0)
// ---------------------------------------------------------------------------
__global__ void init_h0_kernel(const float* __restrict__ h0) {
    int v = blockIdx.x * blockDim.x + threadIdx.x;
    int e = v * 4;
    float4 h = *(const float4*)(h0 + e);
    float vv[4] = {h.x, h.y, h.z, h.w};
    union { __half b[4]; uint2 u2; } phi;
#pragma unroll
    for (int x = 0; x < 4; x++) phi.b[x] = __float2half(vv[x]);
    *(uint2*)(g_A0 + e) = phi.u2;
}

// ---------------------------------------------------------------------------
// Fused LSTM step: 128x128 HMMA GEMM over K=1024 + in-register cell update.
// 8 warps (2Mx4N, warp tile 64x32), CHUNK=32, NSTAGE=4, B streamed from
// gmem in fragment order, single-pass fp16. cin = c0 (step 0) or g_cbuf.
// ---------------------------------------------------------------------------
__global__ __launch_bounds__(256, 2) void lstm_step_kernel(
    const __half* __restrict__ Acur,
    __half* __restrict__ Anext,          // nullptr on last step
    const float* __restrict__ cin,       // c0 (t=0) or g_cbuf
    const float* __restrict__ obs_t,
    float* __restrict__ hout) {
    extern __shared__ __align__(128) char dyn[];
    const int tid = threadIdx.x;
    const int wid = tid >> 5, lane = tid & 31;
    const int warpM = wid >> 2, warpN = wid & 3;   // 2 x 4 warp grid
    const int bRow = blockIdx.x * TILE_M;

    const uint32_t base = smem_u32(dyn);

    // A ldmatrix per-thread address: rows (g&1)*8+jj of warp's 64, 16B half g>>1
    const int g = lane >> 3, jj = lane & 7;
    const uint32_t aoff = (uint32_t)((warpM * 64 + ((g & 1) << 3) + jj) * ROWB
                                     + ((g >> 1) << 4));

    float acc[4][4][4];
#pragma unroll
    for (int m = 0; m < 4; m++)
#pragma unroll
        for (int n = 0; n < 4; n++)
#pragma unroll
            for (int x = 0; x < 4; x++) acc[m][n][x] = 0.f;

    // A loader: thread covers 32B of row lr at col half lc
    const int lr = tid >> 1;
    const int lc = (tid & 1) * 2;
    const __half* asrc = Acur + (size_t)(bRow + lr) * K1 + lc * 8;
    const uint32_t adst = base + lr * ROWB + lc * 16;

    // B fragment stream pointer: advances 64 uint4 (1KB) per kt-step
    const uint4* bp = g_Wfrag
        + ((size_t)(blockIdx.y * 4 + warpN) * 64 * 32 + lane) * 2;

    // Preload B for kt-step 0
    uint32_t bR[2][8];
    {
        uint4 t0 = bp[0], t1 = bp[1];
        bp += 64;
        bR[0][0] = t0.x; bR[0][1] = t0.y; bR[0][2] = t0.z; bR[0][3] = t0.w;
        bR[0][4] = t1.x; bR[0][5] = t1.y; bR[0][6] = t1.z; bR[0][7] = t1.w;
    }

    // Prologue: A chunks 0..2 into stages 0..2
#pragma unroll
    for (int s = 0; s < NSTAGE - 1; s++) {
        uint32_t so = s * STAGE_BYTES;
        int k0 = s * CHUNK;
        cp16(adst + so, asrc + k0);
        cp16(adst + so + 16, asrc + k0 + 8);
        asm volatile("cp.async.commit_group;" ::: "memory");
    }

#pragma unroll 4
    for (int it = 0; it < NCHUNK; ++it) {
        asm volatile("cp.async.wait_group 2;" ::: "memory");
        __syncthreads();
        const uint32_t so = (uint32_t)(it & (NSTAGE - 1)) * STAGE_BYTES;

        // Prefetch A chunk it+3
        {
            int nl = it + NSTAGE - 1;
            if (nl < NCHUNK) {
                uint32_t so2 = (uint32_t)(nl & (NSTAGE - 1)) * STAGE_BYTES;
                int k0 = nl * CHUNK;
                cp16(adst + so2, asrc + k0);
                cp16(adst + so2 + 16, asrc + k0 + 8);
            }
            asm volatile("cp.async.commit_group;" ::: "memory");
        }

#pragma unroll
        for (int kt = 0; kt < 2; kt++) {
            const int cur = (it * 2 + kt) & 1, nxt = cur ^ 1;

            // Prefetch next kt-step's B fragments (1KB/warp, L2-resident).
            // Padding at the end of g_Wfrag covers the final over-read.
            uint4 t0 = bp[0], t1 = bp[1];
            bp += 64;

            // A fragments for this kt
            uint32_t aF[4][4];
            const uint32_t aA = base + so + aoff + kt * 32;
#pragma unroll
            for (int m = 0; m < 4; m++) ldsm4(aF[m], aA + m * 16 * ROWB);

#pragma unroll
            for (int m = 0; m < 4; m++)
#pragma unroll
                for (int n = 0; n < 4; n++)
                    mma16816(acc[m][n], aF[m], bR[cur][n * 2], bR[cur][n * 2 + 1]);

            bR[nxt][0] = t0.x; bR[nxt][1] = t0.y; bR[nxt][2] = t0.z; bR[nxt][3] = t0.w;
            bR[nxt][4] = t1.x; bR[nxt][5] = t1.y; bR[nxt][6] = t1.z; bR[nxt][7] = t1.w;
        }
    }

    // ------------------ fused LSTM epilogue (all in registers) ------------------
    const int q = lane & 3;
    const int u0 = blockIdx.y * 32 + warpN * 8 + 2 * q;    // 2 units: u0, u0+1
    const int rbase = bRow + warpM * 64 + (lane >> 2);

    float wcx[2][4], wcy[2][4], bcv[2][4];
#pragma unroll
    for (int i = 0; i < 2; i++)
#pragma unroll
        for (int gg = 0; gg < 4; gg++) {
            int j = (gg << 10) + u0 + i;
            float2 w = *(const float2*)(g_Wc + j * 2);
            wcx[i][gg] = w.x; wcy[i][gg] = w.y; bcv[i][gg] = g_bc[j];
        }

#pragma unroll
    for (int m = 0; m < 4; m++)
#pragma unroll
        for (int s = 0; s < 2; s++) {
            int b = rbase + m * 16 + s * 8;
            float2 ob = *(const float2*)(obs_t + b * 2);
            float2 cold = *(const float2*)(cin + (size_t)b * HID + u0);
            float cprev[2] = {cold.x, cold.y};
            float cn[2], hn[2];
#pragma unroll
            for (int i = 0; i < 2; i++) {
                float gv[4];
#pragma unroll
                for (int gg = 0; gg < 4; gg++)
                    gv[gg] = acc[m][gg][s * 2 + i]
                           + ob.x * wcx[i][gg] + ob.y * wcy[i][gg] + bcv[i][gg];
                float ig = sigm(gv[0]);
                float fg = sigm(gv[1]);
                float gc = tanh_f(gv[2]);
                float og = sigm(gv[3]);
                cn[i] = fg * cprev[i] + ig * gc;
                hn[i] = og * tanh_f(cn[i]);
            }
            *(float2*)(g_cbuf + (size_t)b * HID + u0) = make_float2(cn[0], cn[1]);
            if (hout)
                *(float2*)(hout + (size_t)b * HID + u0) = make_float2(hn[0], hn[1]);

            if (Anext) {
                union { __half h[2]; uint32_t u; } phi;
#pragma unroll
                for (int i = 0; i < 2; i++) phi.h[i] = __float2half(hn[i]);
                *(uint32_t*)(Anext + (size_t)b * K1 + u0) = phi.u;
            }
        }
}

// ---------------------------------------------------------------------------
extern "C" void kernel_launch(void* const* d_in, const int* in_sizes, int n_in,
                              void* d_out, int out_size) {
    const float* obs   = (const float*)d_in[0];
    const float* h0    = (const float*)d_in[1];
    const float* c0    = (const float*)d_in[2];
    const float* W_emb = (const float*)d_in[3];
    const float* b_emb = (const float*)d_in[4];
    const float* W_ih  = (const float*)d_in[5];
    const float* W_hh  = (const float*)d_in[6];
    const float* b_ih  = (const float*)d_in[7];
    const float* b_hh  = (const float*)d_in[8];

    float* cbuf;
    __half *a0, *a1;
    cudaGetSymbolAddress((void**)&cbuf, g_cbuf);
    cudaGetSymbolAddress((void**)&a0, g_A0);
    cudaGetSymbolAddress((void**)&a1, g_A1);

    prep_wc_kernel<<<512, 256>>>(W_emb, b_emb, W_ih, b_ih, b_hh);
    prep_wfrag_kernel<<<512, 256>>>(W_hh);
    init_h0_kernel<<<BATCH * HID / 4 / 256, 256>>>(h0);

    cudaFuncSetAttribute(lstm_step_kernel,
                         cudaFuncAttributeMaxDynamicSharedMemorySize, SMEM_DYN);

    dim3 grid(BATCH / TILE_M, HID / 32);   // (16, 32)
    __half* bufs[2] = {a0, a1};
    for (int t = 0; t < OBS_LEN; t++) {
        const float* cin = (t == 0) ? c0 : cbuf;
        __half* Anext = (t == OBS_LEN - 1) ? nullptr : bufs[(t + 1) & 1];
        lstm_step_kernel<<<grid, 256, SMEM_DYN>>>(
            bufs[t & 1], Anext, cin,
            obs + (size_t)t * BATCH * 2,
            (t == OBS_LEN - 1) ? (float*)d_out : nullptr);
    }
}